// round 4
// baseline (speedup 1.0000x reference)
#include <cuda_runtime.h>

#define BATCH 64
#define SEQ   64
#define EMBED 1024
#define NHEAD 16
#define HDIM  64
#define VOCAB 50257
#define M_TOT (BATCH*SEQ)   /* 4096 */

typedef unsigned long long u64;

// ---------------- scratch (no allocation allowed) ----------------
__device__ float g_emb[M_TOT*EMBED];
__device__ float g_q  [M_TOT*EMBED];
__device__ float g_k  [M_TOT*EMBED];
__device__ float g_v  [M_TOT*EMBED];
__device__ float g_cat[M_TOT*EMBED];
__device__ float g_y  [M_TOT*EMBED];

// ---------------- f32x2 helpers (Blackwell packed fp32) ----------------
__device__ __forceinline__ u64 pack2(float x, float y) {
    u64 r;
    asm("mov.b64 %0, {%1, %2};" : "=l"(r) : "f"(x), "f"(y));
    return r;
}
__device__ __forceinline__ void unpack2(u64 v, float& x, float& y) {
    asm("mov.b64 {%0, %1}, %2;" : "=f"(x), "=f"(y) : "l"(v));
}
__device__ __forceinline__ void fma2(u64& d, u64 a, u64 b) {
    asm("fma.rn.f32x2 %0, %1, %2, %0;" : "+l"(d) : "l"(a), "l"(b));
}

// ---------------- embed: emb[b,s,:] = E[x[b,s],:] + pe[s,:] ----------------
__global__ void __launch_bounds__(256) embed_kernel(const int* __restrict__ x,
                                                    const float* __restrict__ E,
                                                    const float* __restrict__ pe)
{
    int idx = blockIdx.x * 256 + threadIdx.x;     // float4 index, 0 .. 4096*256-1
    int row = idx >> 8;                            // 0..4095
    int c   = (idx & 255) << 2;                    // 0..1020
    int tok = x[row];
    float4 e = *(const float4*)(E  + (size_t)tok * EMBED + c);
    float4 p = *(const float4*)(pe + (size_t)(row & 63) * EMBED + c);
    e.x += p.x; e.y += p.y; e.z += p.z; e.w += p.w;
    *(float4*)(g_emb + (size_t)row * EMBED + c) = e;
}

// ---------------- shared 128x128x16 inner product on FFMA2 ----------------
__device__ __forceinline__ void mm_tile(const float (&sA)[16][128],
                                        const float (&sB)[16][128],
                                        u64 (&acc)[8][4], int tx, int ty)
{
    #pragma unroll
    for (int kk = 0; kk < 16; kk++) {
        float4 a0 = *(const float4*)(&sA[kk][ty * 8]);
        float4 a1 = *(const float4*)(&sA[kk][ty * 8 + 4]);
        float4 b0 = *(const float4*)(&sB[kk][tx * 8]);
        float4 b1 = *(const float4*)(&sB[kk][tx * 8 + 4]);
        u64 bb0 = pack2(b0.x, b0.y), bb1 = pack2(b0.z, b0.w);
        u64 bb2 = pack2(b1.x, b1.y), bb3 = pack2(b1.z, b1.w);
        float a[8] = {a0.x, a0.y, a0.z, a0.w, a1.x, a1.y, a1.z, a1.w};
        #pragma unroll
        for (int i = 0; i < 8; i++) {
            u64 ai = pack2(a[i], a[i]);
            fma2(acc[i][0], ai, bb0);
            fma2(acc[i][1], ai, bb1);
            fma2(acc[i][2], ai, bb2);
            fma2(acc[i][3], ai, bb3);
        }
    }
}

// ---------------- QKV projection: out[b,h,s,e] = emb @ Wq[h] + bq[h] ----------------
// W layout: [H][D][hd]; logical B(d, n) = W[(n>>6)*D*hd + d*hd + (n&63)], n = h*64+e
__global__ void __launch_bounds__(256) qkv_gemm(const float* __restrict__ W,
                                                const float* __restrict__ bias,
                                                int which)
{
    __shared__ float sA[16][128];
    __shared__ float sB[16][128];
    float* out = (which == 0) ? g_q : (which == 1) ? g_k : g_v;
    int tid = threadIdx.x;
    int tx = tid & 15, ty = tid >> 4;
    int m0 = blockIdx.x * 128;
    int n0 = blockIdx.y * 128;
    u64 acc[8][4] = {};
    for (int k0 = 0; k0 < EMBED; k0 += 16) {
        #pragma unroll
        for (int i = 0; i < 2; i++) {
            int idx = tid + i * 256;
            int r = idx >> 2, c = (idx & 3) << 2;
            float4 v = *(const float4*)(g_emb + (size_t)(m0 + r) * EMBED + k0 + c);
            sA[c + 0][r] = v.x; sA[c + 1][r] = v.y; sA[c + 2][r] = v.z; sA[c + 3][r] = v.w;
        }
        #pragma unroll
        for (int i = 0; i < 2; i++) {
            int idx = tid + i * 256;
            int br = idx >> 5, bc = (idx & 31) << 2;
            int n = n0 + bc;
            float4 v = *(const float4*)(W + (size_t)(n >> 6) * (EMBED * HDIM)
                                          + (size_t)(k0 + br) * HDIM + (n & 63));
            *(float4*)(&sB[br][bc]) = v;
        }
        __syncthreads();
        mm_tile(sA, sB, acc, tx, ty);
        __syncthreads();
    }
    #pragma unroll
    for (int i = 0; i < 8; i++) {
        int m = m0 + ty * 8 + i;
        int b = m >> 6, s = m & 63;
        #pragma unroll
        for (int j = 0; j < 4; j++) {
            float x0, x1;
            unpack2(acc[i][j], x0, x1);
            int n = n0 + tx * 8 + j * 2;
            int h = n >> 6, e = n & 63;
            float* dst = out + (size_t)(((b * NHEAD + h) * SEQ + s) * HDIM + e);
            dst[0] = x0 + bias[n];
            dst[1] = x1 + bias[n + 1];
        }
    }
}

// ---------------- attention: one block per (b,h) ----------------
__global__ void __launch_bounds__(256) attn_kernel()
{
    __shared__ float sQ [64][68];   // pad 68: conflict-free + 16B aligned rows
    __shared__ float sKV[64][68];
    int bh  = blockIdx.x;
    int tid = threadIdx.x;
    const float* qb = g_q + (size_t)bh * (SEQ * HDIM);
    const float* kb = g_k + (size_t)bh * (SEQ * HDIM);
    const float* vb = g_v + (size_t)bh * (SEQ * HDIM);
    #pragma unroll
    for (int i = 0; i < 4; i++) {
        int idx = tid + i * 256;
        int r = idx >> 4, c = (idx & 15) << 2;
        *(float4*)(&sQ [r][c]) = *(const float4*)(qb + r * 64 + c);
        *(float4*)(&sKV[r][c]) = *(const float4*)(kb + r * 64 + c);
    }
    __syncthreads();

    int s = tid >> 2, q = tid & 3;   // thread handles row s, columns t = q + 4j
    float4 qv[16];
    #pragma unroll
    for (int k4 = 0; k4 < 16; k4++) qv[k4] = *(const float4*)(&sQ[s][k4 * 4]);

    float sc[16];
    #pragma unroll
    for (int j = 0; j < 16; j++) {
        int t = q + 4 * j;
        float d = 0.f;
        #pragma unroll
        for (int k4 = 0; k4 < 16; k4++) {
            float4 kv = *(const float4*)(&sKV[t][k4 * 4]);
            d += qv[k4].x * kv.x + qv[k4].y * kv.y + qv[k4].z * kv.z + qv[k4].w * kv.w;
        }
        sc[j] = (t <= s) ? d * 0.125f : -1e30f;   // causal mask + 1/sqrt(64)
    }
    // softmax across the 4-lane group that shares row s
    float mx = sc[0];
    #pragma unroll
    for (int j = 1; j < 16; j++) mx = fmaxf(mx, sc[j]);
    mx = fmaxf(mx, __shfl_xor_sync(0xFFFFFFFFu, mx, 1));
    mx = fmaxf(mx, __shfl_xor_sync(0xFFFFFFFFu, mx, 2));
    float sum = 0.f;
    #pragma unroll
    for (int j = 0; j < 16; j++) { sc[j] = __expf(sc[j] - mx); sum += sc[j]; }
    sum += __shfl_xor_sync(0xFFFFFFFFu, sum, 1);
    sum += __shfl_xor_sync(0xFFFFFFFFu, sum, 2);
    float inv = 1.f / sum;
    #pragma unroll
    for (int j = 0; j < 16; j++) sc[j] *= inv;

    __syncthreads();   // done with K
    #pragma unroll
    for (int i = 0; i < 4; i++) {
        int idx = tid + i * 256;
        int r = idx >> 4, c = (idx & 15) << 2;
        *(float4*)(&sKV[r][c]) = *(const float4*)(vb + r * 64 + c);
    }
    __syncthreads();

    float po[64];
    #pragma unroll
    for (int e = 0; e < 64; e++) po[e] = 0.f;
    #pragma unroll
    for (int j = 0; j < 16; j++) {
        int t = q + 4 * j;
        float w = sc[j];
        #pragma unroll
        for (int e4 = 0; e4 < 16; e4++) {
            float4 v = *(const float4*)(&sKV[t][e4 * 4]);
            po[e4 * 4 + 0] += w * v.x;
            po[e4 * 4 + 1] += w * v.y;
            po[e4 * 4 + 2] += w * v.z;
            po[e4 * 4 + 3] += w * v.w;
        }
    }
    #pragma unroll
    for (int e = 0; e < 64; e++) {
        po[e] += __shfl_xor_sync(0xFFFFFFFFu, po[e], 1);
        po[e] += __shfl_xor_sync(0xFFFFFFFFu, po[e], 2);
    }
    // write to cat layout [B,S,H*hd]; this thread owns e in [16q, 16q+16)
    int b = bh >> 4, h = bh & 15;
    float* dst = g_cat + (size_t)b * (SEQ * EMBED) + (size_t)s * EMBED + h * HDIM + q * 16;
    #pragma unroll
    for (int i = 0; i < 4; i++) {
        int e0 = q * 16 + i * 4;
        *(float4*)(dst + i * 4) = make_float4(po[e0], po[e0 + 1], po[e0 + 2], po[e0 + 3]);
    }
}

// ---------------- output projection + residual: y = cat @ Wo + bo + emb ----------------
__global__ void __launch_bounds__(256) wo_gemm(const float* __restrict__ Wo,
                                               const float* __restrict__ bo)
{
    __shared__ float sA[16][128];
    __shared__ float sB[16][128];
    int tid = threadIdx.x;
    int tx = tid & 15, ty = tid >> 4;
    int m0 = blockIdx.x * 128;
    int n0 = blockIdx.y * 128;
    u64 acc[8][4] = {};
    for (int k0 = 0; k0 < EMBED; k0 += 16) {
        #pragma unroll
        for (int i = 0; i < 2; i++) {
            int idx = tid + i * 256;
            int r = idx >> 2, c = (idx & 3) << 2;
            float4 v = *(const float4*)(g_cat + (size_t)(m0 + r) * EMBED + k0 + c);
            sA[c + 0][r] = v.x; sA[c + 1][r] = v.y; sA[c + 2][r] = v.z; sA[c + 3][r] = v.w;
        }
        #pragma unroll
        for (int i = 0; i < 2; i++) {
            int idx = tid + i * 256;
            int br = idx >> 5, bc = (idx & 31) << 2;
            *(float4*)(&sB[br][bc]) =
                *(const float4*)(Wo + (size_t)(k0 + br) * EMBED + n0 + bc);
        }
        __syncthreads();
        mm_tile(sA, sB, acc, tx, ty);
        __syncthreads();
    }
    #pragma unroll
    for (int i = 0; i < 8; i++) {
        int m = m0 + ty * 8 + i;
        size_t rowoff = (size_t)m * EMBED;
        #pragma unroll
        for (int j = 0; j < 4; j++) {
            float x0, x1;
            unpack2(acc[i][j], x0, x1);
            int n = n0 + tx * 8 + j * 2;
            g_y[rowoff + n]     = x0 + bo[n]     + g_emb[rowoff + n];
            g_y[rowoff + n + 1] = x1 + bo[n + 1] + g_emb[rowoff + n + 1];
        }
    }
}

// ---------------- logits: out = y @ Wu + bu  (the 421-GFLOP kernel) ----------------
// NOTE: Wu rows have stride 50257 floats (odd) -> rows are only 4-byte aligned.
// All Wu traffic must use scalar 32-bit loads; float4 loads trap (misaligned).
__global__ void __launch_bounds__(256) wu_gemm(const float* __restrict__ Wu,
                                               const float* __restrict__ bu,
                                               float* __restrict__ out)
{
    __shared__ float sA[16][128];
    __shared__ float sB[16][128];
    int tid = threadIdx.x;
    int tx = tid & 15, ty = tid >> 4;
    int m0 = blockIdx.x * 128;
    int n0 = blockIdx.y * 128;
    u64 acc[8][4] = {};
    for (int k0 = 0; k0 < EMBED; k0 += 16) {
        #pragma unroll
        for (int i = 0; i < 2; i++) {
            int idx = tid + i * 256;
            int r = idx >> 2, c = (idx & 3) << 2;
            float4 v = *(const float4*)(g_y + (size_t)(m0 + r) * EMBED + k0 + c);
            sA[c + 0][r] = v.x; sA[c + 1][r] = v.y; sA[c + 2][r] = v.z; sA[c + 3][r] = v.w;
        }
        // B tile: scalar loads only (odd row stride => 4B alignment)
        #pragma unroll
        for (int i = 0; i < 2; i++) {
            int idx = tid + i * 256;
            int br = idx >> 5, bc = (idx & 31) << 2;
            const float* src = Wu + (size_t)(k0 + br) * VOCAB;
            #pragma unroll
            for (int jj = 0; jj < 4; jj++) {
                int n = n0 + bc + jj;
                sB[br][bc + jj] = (n < VOCAB) ? __ldg(src + n) : 0.f;
            }
        }
        __syncthreads();
        mm_tile(sA, sB, acc, tx, ty);
        __syncthreads();
    }
    #pragma unroll
    for (int i = 0; i < 8; i++) {
        int m = m0 + ty * 8 + i;
        size_t rowoff = (size_t)m * VOCAB;
        #pragma unroll
        for (int j = 0; j < 4; j++) {
            float x0, x1;
            unpack2(acc[i][j], x0, x1);
            int n = n0 + tx * 8 + j * 2;
            if (n < VOCAB)     out[rowoff + n]     = x0 + bu[n];
            if (n + 1 < VOCAB) out[rowoff + n + 1] = x1 + bu[n + 1];
        }
    }
}

// ---------------- launch ----------------
extern "C" void kernel_launch(void* const* d_in, const int* in_sizes, int n_in,
                              void* d_out, int out_size)
{
    const int*   x  = (const int*)  d_in[0];
    const float* E  = (const float*)d_in[1];
    const float* pe = (const float*)d_in[2];
    const float* Wq = (const float*)d_in[3];
    const float* bq = (const float*)d_in[4];
    const float* Wk = (const float*)d_in[5];
    const float* bk = (const float*)d_in[6];
    const float* Wv = (const float*)d_in[7];
    const float* bv = (const float*)d_in[8];
    const float* Wo = (const float*)d_in[9];
    const float* bo = (const float*)d_in[10];
    const float* Wu = (const float*)d_in[11];
    const float* bu = (const float*)d_in[12];
    float* out = (float*)d_out;

    embed_kernel<<<4096, 256>>>(x, E, pe);

    dim3 gq(M_TOT / 128, EMBED / 128);            // (32, 8)
    qkv_gemm<<<gq, 256>>>(Wq, bq, 0);
    qkv_gemm<<<gq, 256>>>(Wk, bk, 1);
    qkv_gemm<<<gq, 256>>>(Wv, bv, 2);

    attn_kernel<<<BATCH * NHEAD, 256>>>();

    wo_gemm<<<dim3(M_TOT / 128, EMBED / 128), 256>>>(Wo, bo);

    dim3 gu(M_TOT / 128, (VOCAB + 127) / 128);    // (32, 393)
    wu_gemm<<<gu, 256>>>(Wu, bu, out);
}